// round 5
// baseline (speedup 1.0000x reference)
#include <cuda_runtime.h>
#include <cuda_fp16.h>
#include <math.h>

#define N_NODES 50000
#define N_EDGES 800000
#define DIN 128
#define NH 4

// ---------------- scratch buffers -------------------------------------------
__device__ __half g_feath[(size_t)N_NODES * 256];  // GEMM output fp16 (max HF=256)
__device__ float  g_bufA[(size_t)N_NODES * 128];
__device__ float  g_bufB[(size_t)N_NODES * 128];
__device__ float  g_el[(size_t)N_NODES * NH];
__device__ float  g_er[(size_t)N_NODES * NH];
__device__ int    g_cnt[N_NODES];                  // zero-init at load; re-zeroed by scan
__device__ int    g_rptr[N_NODES + 1];
__device__ int    g_cursor[N_NODES];
__device__ int    g_srcs[N_EDGES];

__device__ __forceinline__ float lrelu(float v) { return v > 0.f ? v : 0.2f * v; }

// ---------------- tensor-core GEMM + fused el/er -----------------------------
template<int F>
__global__ void __launch_bounds__(256, 2)
tc_gemm(const float* __restrict__ h, const float* __restrict__ W,
        const float* __restrict__ al, const float* __restrict__ ar,
        __half* __restrict__ feat, float* __restrict__ el,
        float* __restrict__ er) {
    constexpr int HF = 4 * F;
    constexpr int HT = 128 / F;
    extern __shared__ __half smx[];
    __half* As = smx;                      // [128][136]
    __half* Bs = smx + 128 * 136;          // [128][136] n-major over k, swizzled
    float* sAL = (float*)(smx + 2 * 128 * 136);
    float* sAR = sAL + 128;

    const int ct  = blockIdx.y;
    const int n0  = blockIdx.x * 128;
    const int tid = threadIdx.x;
    const int lane = tid & 31;
    const int wid  = tid >> 5;

    if (tid < 128) { sAL[tid] = al[ct * 128 + tid]; sAR[tid] = ar[ct * 128 + tid]; }

#pragma unroll
    for (int i = 0; i < 16; i++) {
        int idx = tid + i * 256;
        int j = idx * 4;
        int r = j >> 7, c = j & 127;
        int n = n0 + r;
        float4 v = make_float4(0.f, 0.f, 0.f, 0.f);
        if (n < N_NODES) v = *(const float4*)&h[(size_t)n * DIN + c];
        __half2* p = (__half2*)&As[r * 136 + c];
        p[0] = __floats2half2_rn(v.x, v.y);
        p[1] = __floats2half2_rn(v.z, v.w);
    }
#pragma unroll
    for (int i = 0; i < 32; i++) {
        int t = tid + i * 256;
        int n = t & 127, kp = t >> 7;
        int k = kp * 2;
        float f0 = W[(size_t)k * HF + ct * 128 + n];
        float f1 = W[(size_t)(k + 1) * HF + ct * 128 + n];
        int kps = kp ^ ((n >> 3) & 3);
        *(__half2*)&Bs[n * 136 + kps * 2] = __floats2half2_rn(f0, f1);
    }
    __syncthreads();

    const int g = lane >> 2, q = lane & 3;
    const int m0 = wid * 16;
    float acc[16][4];
#pragma unroll
    for (int nt = 0; nt < 16; nt++)
        acc[nt][0] = acc[nt][1] = acc[nt][2] = acc[nt][3] = 0.f;

#pragma unroll
    for (int ks = 0; ks < 8; ks++) {
        unsigned a0 = *(const unsigned*)&As[(m0 + g)     * 136 + ks * 16 + q * 2];
        unsigned a1 = *(const unsigned*)&As[(m0 + 8 + g) * 136 + ks * 16 + q * 2];
        unsigned a2 = *(const unsigned*)&As[(m0 + g)     * 136 + ks * 16 + 8 + q * 2];
        unsigned a3 = *(const unsigned*)&As[(m0 + 8 + g) * 136 + ks * 16 + 8 + q * 2];
#pragma unroll
        for (int nt = 0; nt < 16; nt++) {
            int n = nt * 8 + g;
            int sw = nt & 3;
            int p0 = (ks * 8 + q) ^ sw;
            int p1 = (ks * 8 + 4 + q) ^ sw;
            unsigned b0 = *(const unsigned*)&Bs[n * 136 + p0 * 2];
            unsigned b1 = *(const unsigned*)&Bs[n * 136 + p1 * 2];
            asm volatile(
                "mma.sync.aligned.m16n8k16.row.col.f32.f16.f16.f32 "
                "{%0,%1,%2,%3}, {%4,%5,%6,%7}, {%8,%9}, {%0,%1,%2,%3};"
                : "+f"(acc[nt][0]), "+f"(acc[nt][1]), "+f"(acc[nt][2]), "+f"(acc[nt][3])
                : "r"(a0), "r"(a1), "r"(a2), "r"(a3), "r"(b0), "r"(b1));
        }
    }

    const int rA = n0 + m0 + g, rB = rA + 8;

#pragma unroll
    for (int nt = 0; nt < 16; nt++) {
        int col = ct * 128 + nt * 8 + q * 2;
        if (rA < N_NODES)
            *(__half2*)&feat[(size_t)rA * HF + col] = __floats2half2_rn(acc[nt][0], acc[nt][1]);
        if (rB < N_NODES)
            *(__half2*)&feat[(size_t)rB * HF + col] = __floats2half2_rn(acc[nt][2], acc[nt][3]);
    }
#pragma unroll
    for (int hh = 0; hh < HT; hh++) {
        float plA = 0.f, prA = 0.f, plB = 0.f, prB = 0.f;
#pragma unroll
        for (int j = 0; j < F / 8; j++) {
            int nt = hh * (F / 8) + j;
            int c = nt * 8 + q * 2;
            float al0 = sAL[c], al1 = sAL[c + 1];
            float ar0 = sAR[c], ar1 = sAR[c + 1];
            plA += acc[nt][0] * al0 + acc[nt][1] * al1;
            prA += acc[nt][0] * ar0 + acc[nt][1] * ar1;
            plB += acc[nt][2] * al0 + acc[nt][3] * al1;
            prB += acc[nt][2] * ar0 + acc[nt][3] * ar1;
        }
        plA += __shfl_xor_sync(~0u, plA, 1); plA += __shfl_xor_sync(~0u, plA, 2);
        prA += __shfl_xor_sync(~0u, prA, 1); prA += __shfl_xor_sync(~0u, prA, 2);
        plB += __shfl_xor_sync(~0u, plB, 1); plB += __shfl_xor_sync(~0u, plB, 2);
        prB += __shfl_xor_sync(~0u, prB, 1); prB += __shfl_xor_sync(~0u, prB, 2);
        if (q == 0) {
            int head = ct * HT + hh;
            if (rA < N_NODES) { el[rA * 4 + head] = plA; er[rA * 4 + head] = prA; }
            if (rB < N_NODES) { el[rB * 4 + head] = plB; er[rB * 4 + head] = prB; }
        }
    }
}

// ---------------- CSR build --------------------------------------------------
__global__ void hist_kernel(const int* __restrict__ dst) {
    int e = blockIdx.x * blockDim.x + threadIdx.x;
    if (e < N_EDGES) atomicAdd(&g_cnt[dst[e]], 1);
}
// single-block chained scan; re-zeroes g_cnt for the next kernel_launch call
__global__ void scan_kernel() {
    __shared__ int wsum[32];
    __shared__ int carry;
    int t = threadIdx.x;
    if (t == 0) carry = 0;
    __syncthreads();
    for (int base = 0; base < N_NODES; base += 1024) {
        int i = base + t;
        int v = (i < N_NODES) ? g_cnt[i] : 0;
        if (i < N_NODES) g_cnt[i] = 0;           // reset for next call
        int x = v;
#pragma unroll
        for (int o = 1; o < 32; o <<= 1) {
            int y = __shfl_up_sync(~0u, x, o);
            if ((t & 31) >= o) x += y;
        }
        if ((t & 31) == 31) wsum[t >> 5] = x;
        __syncthreads();
        if (t < 32) {
            int s = wsum[t];
#pragma unroll
            for (int o = 1; o < 32; o <<= 1) {
                int y = __shfl_up_sync(~0u, s, o);
                if (t >= o) s += y;
            }
            wsum[t] = s;
        }
        __syncthreads();
        int warpoff = (t >= 32) ? wsum[(t >> 5) - 1] : 0;
        int excl = x + warpoff - v + carry;
        if (i < N_NODES) { g_rptr[i] = excl; g_cursor[i] = excl; }
        int btot = wsum[31];
        __syncthreads();
        if (t == 0) carry += btot;
        __syncthreads();
    }
    if (t == 0) g_rptr[N_NODES] = N_EDGES;
}
__global__ void scatter_kernel(const int* __restrict__ src, const int* __restrict__ dst) {
    int e = blockIdx.x * blockDim.x + threadIdx.x;
    if (e >= N_EDGES) return;
    int pos = atomicAdd(&g_cursor[dst[e]], 1);
    g_srcs[pos] = src[e];
}

// ---------------- per-edge step ----------------------------------------------
template<int HF>
__device__ __forceinline__ void edge_step(int s, int lane, int hsel, float4 erv,
                                          const __half2* __restrict__ feat2,
                                          float2 (&acc)[HF / 64], float (&den)[4]) {
    constexpr int Q = HF / 64;
    float4 elv = __ldg((const float4*)&g_el[s * 4]);
    float ex0 = __expf(lrelu(elv.x + erv.x));
    float ex1 = __expf(lrelu(elv.y + erv.y));
    float ex2 = __expf(lrelu(elv.z + erv.z));
    float ex3 = __expf(lrelu(elv.w + erv.w));
    den[0] += ex0; den[1] += ex1; den[2] += ex2; den[3] += ex3;
    const __half2* fp = feat2 + (size_t)s * (HF / 2);
#pragma unroll
    for (int qq = 0; qq < Q; qq++) {
        float ex;
        if (HF == 128) {
            if (qq == 0) ex = hsel ? ex1 : ex0;
            else         ex = hsel ? ex3 : ex2;
        } else {
            ex = (qq == 0) ? ex0 : (qq == 1) ? ex1 : (qq == 2) ? ex2 : ex3;
        }
        float2 f = __half22float2(__ldg(&fp[qq * 32 + lane]));
        acc[qq].x += ex * f.x;
        acc[qq].y += ex * f.y;
    }
}

template<int HF, bool LAST>
__device__ __forceinline__ void node_epilogue(int nid, int lane, float2 (&acc)[HF / 64],
                                              float (&den)[4], const float* __restrict__ bias,
                                              float* __restrict__ out) {
    constexpr int Q = HF / 64;
    float inv[4];
#pragma unroll
    for (int hh = 0; hh < 4; hh++) inv[hh] = 1.f / fmaxf(den[hh], 1e-9f);
    if (!LAST) {
#pragma unroll
        for (int qq = 0; qq < Q; qq++) {
            int j = qq * 32 + lane;
            int hh = j >> 4;
            int col = 2 * j;
            float vx = acc[qq].x * inv[hh] + bias[col];
            float vy = acc[qq].y * inv[hh] + bias[col + 1];
            vx = vx > 0.f ? vx : expm1f(vx);
            vy = vy > 0.f ? vy : expm1f(vy);
            *(float2*)&out[(size_t)nid * HF + col] = make_float2(vx, vy);
        }
    } else {
        float yx = 0.f, yy = 0.f;
#pragma unroll
        for (int qq = 0; qq < Q; qq++) {
            yx += acc[qq].x * inv[qq] + bias[qq * 64 + 2 * lane];
            yy += acc[qq].y * inv[qq] + bias[qq * 64 + 2 * lane + 1];
        }
        *(float2*)&out[(size_t)nid * 64 + 2 * lane] = make_float2(0.25f * yx, 0.25f * yy);
    }
}

// ---------------- GAT aggregation: one warp per TWO dst nodes ----------------
// Two interleaved edge streams per warp -> 2x memory-level parallelism.
template<int HF, bool LAST>
__global__ void gat_agg(const __half* __restrict__ feat, const float* __restrict__ er,
                        const float* __restrict__ bias, float* __restrict__ out) {
    constexpr int Q = HF / 64;
    int warp = (blockIdx.x * blockDim.x + threadIdx.x) >> 5;
    int lane = threadIdx.x & 31;
    const int n0 = 2 * warp;
    if (n0 >= N_NODES) return;
    const int n1 = n0 + 1;
    const bool has1 = n1 < N_NODES;
    const int hsel = lane >> 4;
    const __half2* feat2 = (const __half2*)feat;

    float4 er0 = *(const float4*)&er[n0 * 4];
    float4 er1 = has1 ? *(const float4*)&er[n1 * 4] : make_float4(0, 0, 0, 0);
    int i0 = __ldg(&g_rptr[n0]), e0 = __ldg(&g_rptr[n0 + 1]);
    int i1 = has1 ? e0 : 0, e1 = has1 ? __ldg(&g_rptr[n1 + 1]) : 0;

    float2 acc0[Q], acc1[Q];
    float den0[4] = {0, 0, 0, 0}, den1[4] = {0, 0, 0, 0};
#pragma unroll
    for (int qq = 0; qq < Q; qq++) { acc0[qq] = make_float2(0, 0); acc1[qq] = make_float2(0, 0); }

    // interleaved dual-stream loop (warp-uniform conditions, no divergence)
    while (i0 < e0 && i1 < e1) {
        int s0 = __ldg(&g_srcs[i0]);
        int s1 = __ldg(&g_srcs[i1]);
        edge_step<HF>(s0, lane, hsel, er0, feat2, acc0, den0);
        edge_step<HF>(s1, lane, hsel, er1, feat2, acc1, den1);
        i0++; i1++;
    }
#pragma unroll 2
    for (; i0 < e0; i0++)
        edge_step<HF>(__ldg(&g_srcs[i0]), lane, hsel, er0, feat2, acc0, den0);
#pragma unroll 2
    for (; i1 < e1; i1++)
        edge_step<HF>(__ldg(&g_srcs[i1]), lane, hsel, er1, feat2, acc1, den1);

    node_epilogue<HF, LAST>(n0, lane, acc0, den0, bias, out);
    if (has1) node_epilogue<HF, LAST>(n1, lane, acc1, den1, bias, out);
}

// ---------------- host -------------------------------------------------------
extern "C" void kernel_launch(void* const* d_in, const int* in_sizes, int n_in,
                              void* d_out, int out_size) {
    const float* x   = (const float*)d_in[0];
    const int*   src = (const int*)d_in[1];
    const int*   dst = (const int*)d_in[2];
    const float *W[4], *al[4], *ar[4], *bb[4];
    for (int i = 0; i < 4; i++) {
        W[i]  = (const float*)d_in[3 + i * 4];
        al[i] = (const float*)d_in[4 + i * 4];
        ar[i] = (const float*)d_in[5 + i * 4];
        bb[i] = (const float*)d_in[6 + i * 4];
    }

    __half* feat;
    float *A, *B, *el, *er;
    cudaGetSymbolAddress((void**)&feat, g_feath);
    cudaGetSymbolAddress((void**)&A,    g_bufA);
    cudaGetSymbolAddress((void**)&B,    g_bufB);
    cudaGetSymbolAddress((void**)&el,   g_el);
    cudaGetSymbolAddress((void**)&er,   g_er);

    const int SMEM = 2 * 128 * 136 * 2 + 2 * 128 * 4;   // 70656 B
    cudaFuncSetAttribute(tc_gemm<32>, cudaFuncAttributeMaxDynamicSharedMemorySize, SMEM);
    cudaFuncSetAttribute(tc_gemm<64>, cudaFuncAttributeMaxDynamicSharedMemorySize, SMEM);

    // ---- CSR build (g_cnt zeroed by previous call's scan; static-zero first) ----
    hist_kernel<<<(N_EDGES + 255) / 256, 256>>>(dst);
    scan_kernel<<<1, 1024>>>();
    scatter_kernel<<<(N_EDGES + 255) / 256, 256>>>(src, dst);

    const int agg_blocks = ((N_NODES + 1) / 2 * 32 + 255) / 256;
    const dim3 g1((N_NODES + 127) / 128, 1), g2((N_NODES + 127) / 128, 2);

    // layer 1
    tc_gemm<32><<<g1, 256, SMEM>>>(x, W[0], al[0], ar[0], feat, el, er);
    gat_agg<128, false><<<agg_blocks, 256>>>(feat, er, bb[0], A);
    // layer 2
    tc_gemm<32><<<g1, 256, SMEM>>>(A, W[1], al[1], ar[1], feat, el, er);
    gat_agg<128, false><<<agg_blocks, 256>>>(feat, er, bb[1], B);
    // layer 3
    tc_gemm<32><<<g1, 256, SMEM>>>(B, W[2], al[2], ar[2], feat, el, er);
    gat_agg<128, false><<<agg_blocks, 256>>>(feat, er, bb[2], A);
    // layer 4 (fused head-mean)
    tc_gemm<64><<<g2, 256, SMEM>>>(A, W[3], al[3], ar[3], feat, el, er);
    gat_agg<256, true><<<agg_blocks, 256>>>(feat, er, bb[3], (float*)d_out);
}

// round 6
// speedup vs baseline: 1.3162x; 1.3162x over previous
#include <cuda_runtime.h>
#include <cuda_fp16.h>
#include <math.h>

#define N_NODES 50000
#define N_EDGES 800000
#define DIN 128
#define NH 4

// ---------------- scratch buffers -------------------------------------------
__device__ __half g_feath[(size_t)N_NODES * 256];  // GEMM output fp16 (max HF=256)
__device__ float  g_bufA[(size_t)N_NODES * 128];
__device__ float  g_bufB[(size_t)N_NODES * 128];
__device__ float  g_el[(size_t)N_NODES * NH];
__device__ float  g_er[(size_t)N_NODES * NH];
__device__ int    g_cnt[N_NODES];                  // zero-init; re-zeroed by scan
__device__ int    g_rptr[N_NODES + 1];
__device__ int    g_cursor[N_NODES];
__device__ int    g_srcs[N_EDGES];

// ---------------- tensor-core GEMM + fused el/er -----------------------------
template<int F>
__global__ void __launch_bounds__(256, 2)
tc_gemm(const float* __restrict__ h, const float* __restrict__ W,
        const float* __restrict__ al, const float* __restrict__ ar,
        __half* __restrict__ feat, float* __restrict__ el,
        float* __restrict__ er) {
    constexpr int HF = 4 * F;
    constexpr int HT = 128 / F;
    extern __shared__ __half smx[];
    __half* As = smx;                      // [128][136]
    __half* Bs = smx + 128 * 136;          // [128][136] n-major over k, swizzled
    float* sAL = (float*)(smx + 2 * 128 * 136);
    float* sAR = sAL + 128;

    const int ct  = blockIdx.y;
    const int n0  = blockIdx.x * 128;
    const int tid = threadIdx.x;
    const int lane = tid & 31;
    const int wid  = tid >> 5;

    if (tid < 128) { sAL[tid] = al[ct * 128 + tid]; sAR[tid] = ar[ct * 128 + tid]; }

#pragma unroll
    for (int i = 0; i < 16; i++) {
        int idx = tid + i * 256;
        int j = idx * 4;
        int r = j >> 7, c = j & 127;
        int n = n0 + r;
        float4 v = make_float4(0.f, 0.f, 0.f, 0.f);
        if (n < N_NODES) v = *(const float4*)&h[(size_t)n * DIN + c];
        __half2* p = (__half2*)&As[r * 136 + c];
        p[0] = __floats2half2_rn(v.x, v.y);
        p[1] = __floats2half2_rn(v.z, v.w);
    }
#pragma unroll
    for (int i = 0; i < 32; i++) {
        int t = tid + i * 256;
        int n = t & 127, kp = t >> 7;
        int k = kp * 2;
        float f0 = W[(size_t)k * HF + ct * 128 + n];
        float f1 = W[(size_t)(k + 1) * HF + ct * 128 + n];
        int kps = kp ^ ((n >> 3) & 3);
        *(__half2*)&Bs[n * 136 + kps * 2] = __floats2half2_rn(f0, f1);
    }
    __syncthreads();

    const int g = lane >> 2, q = lane & 3;
    const int m0 = wid * 16;
    float acc[16][4];
#pragma unroll
    for (int nt = 0; nt < 16; nt++)
        acc[nt][0] = acc[nt][1] = acc[nt][2] = acc[nt][3] = 0.f;

#pragma unroll
    for (int ks = 0; ks < 8; ks++) {
        unsigned a0 = *(const unsigned*)&As[(m0 + g)     * 136 + ks * 16 + q * 2];
        unsigned a1 = *(const unsigned*)&As[(m0 + 8 + g) * 136 + ks * 16 + q * 2];
        unsigned a2 = *(const unsigned*)&As[(m0 + g)     * 136 + ks * 16 + 8 + q * 2];
        unsigned a3 = *(const unsigned*)&As[(m0 + 8 + g) * 136 + ks * 16 + 8 + q * 2];
#pragma unroll
        for (int nt = 0; nt < 16; nt++) {
            int n = nt * 8 + g;
            int sw = nt & 3;
            int p0 = (ks * 8 + q) ^ sw;
            int p1 = (ks * 8 + 4 + q) ^ sw;
            unsigned b0 = *(const unsigned*)&Bs[n * 136 + p0 * 2];
            unsigned b1 = *(const unsigned*)&Bs[n * 136 + p1 * 2];
            asm volatile(
                "mma.sync.aligned.m16n8k16.row.col.f32.f16.f16.f32 "
                "{%0,%1,%2,%3}, {%4,%5,%6,%7}, {%8,%9}, {%0,%1,%2,%3};"
                : "+f"(acc[nt][0]), "+f"(acc[nt][1]), "+f"(acc[nt][2]), "+f"(acc[nt][3])
                : "r"(a0), "r"(a1), "r"(a2), "r"(a3), "r"(b0), "r"(b1));
        }
    }

    const int rA = n0 + m0 + g, rB = rA + 8;

#pragma unroll
    for (int nt = 0; nt < 16; nt++) {
        int col = ct * 128 + nt * 8 + q * 2;
        if (rA < N_NODES)
            *(__half2*)&feat[(size_t)rA * HF + col] = __floats2half2_rn(acc[nt][0], acc[nt][1]);
        if (rB < N_NODES)
            *(__half2*)&feat[(size_t)rB * HF + col] = __floats2half2_rn(acc[nt][2], acc[nt][3]);
    }
#pragma unroll
    for (int hh = 0; hh < HT; hh++) {
        float plA = 0.f, prA = 0.f, plB = 0.f, prB = 0.f;
#pragma unroll
        for (int j = 0; j < F / 8; j++) {
            int nt = hh * (F / 8) + j;
            int c = nt * 8 + q * 2;
            float al0 = sAL[c], al1 = sAL[c + 1];
            float ar0 = sAR[c], ar1 = sAR[c + 1];
            plA += acc[nt][0] * al0 + acc[nt][1] * al1;
            prA += acc[nt][0] * ar0 + acc[nt][1] * ar1;
            plB += acc[nt][2] * al0 + acc[nt][3] * al1;
            prB += acc[nt][2] * ar0 + acc[nt][3] * ar1;
        }
        plA += __shfl_xor_sync(~0u, plA, 1); plA += __shfl_xor_sync(~0u, plA, 2);
        prA += __shfl_xor_sync(~0u, prA, 1); prA += __shfl_xor_sync(~0u, prA, 2);
        plB += __shfl_xor_sync(~0u, plB, 1); plB += __shfl_xor_sync(~0u, plB, 2);
        prB += __shfl_xor_sync(~0u, prB, 1); prB += __shfl_xor_sync(~0u, prB, 2);
        if (q == 0) {
            int head = ct * HT + hh;
            if (rA < N_NODES) { el[rA * 4 + head] = plA; er[rA * 4 + head] = prA; }
            if (rB < N_NODES) { el[rB * 4 + head] = plB; er[rB * 4 + head] = prB; }
        }
    }
}

// ---------------- CSR build --------------------------------------------------
__global__ void hist_kernel(const int* __restrict__ dst) {
    int e = blockIdx.x * blockDim.x + threadIdx.x;
    if (e < N_EDGES) atomicAdd(&g_cnt[dst[e]], 1);
}
__global__ void scan_kernel() {
    __shared__ int wsum[32];
    __shared__ int carry;
    int t = threadIdx.x;
    if (t == 0) carry = 0;
    __syncthreads();
    for (int base = 0; base < N_NODES; base += 1024) {
        int i = base + t;
        int v = (i < N_NODES) ? g_cnt[i] : 0;
        if (i < N_NODES) g_cnt[i] = 0;           // reset for next call
        int x = v;
#pragma unroll
        for (int o = 1; o < 32; o <<= 1) {
            int y = __shfl_up_sync(~0u, x, o);
            if ((t & 31) >= o) x += y;
        }
        if ((t & 31) == 31) wsum[t >> 5] = x;
        __syncthreads();
        if (t < 32) {
            int s = wsum[t];
#pragma unroll
            for (int o = 1; o < 32; o <<= 1) {
                int y = __shfl_up_sync(~0u, s, o);
                if (t >= o) s += y;
            }
            wsum[t] = s;
        }
        __syncthreads();
        int warpoff = (t >= 32) ? wsum[(t >> 5) - 1] : 0;
        int excl = x + warpoff - v + carry;
        if (i < N_NODES) { g_rptr[i] = excl; g_cursor[i] = excl; }
        int btot = wsum[31];
        __syncthreads();
        if (t == 0) carry += btot;
        __syncthreads();
    }
    if (t == 0) g_rptr[N_NODES] = N_EDGES;
}
__global__ void scatter_kernel(const int* __restrict__ src, const int* __restrict__ dst) {
    int e = blockIdx.x * blockDim.x + threadIdx.x;
    if (e >= N_EDGES) return;
    int pos = atomicAdd(&g_cursor[dst[e]], 1);
    g_srcs[pos] = src[e];
}

// ---------------- GAT aggregation: one warp per dst node ---------------------
// Lane-specialized attention: lane l computes the softmax exponent only for
// head (l&3) -> ONE exp per edge per warp; multipliers fetched via width-4
// shuffles. Lane l gathers feat cols 4l..4l+3 (one LDG.64 per edge, HF=128).
template<bool LAST>
__global__ void gat_agg(const __half* __restrict__ feat, const float* __restrict__ el,
                        const float* __restrict__ er, const float* __restrict__ bias,
                        float* __restrict__ out) {
    constexpr int HF = LAST ? 256 : 128;
    int warp = (blockIdx.x * blockDim.x + threadIdx.x) >> 5;
    int lane = threadIdx.x & 31;
    if (warp >= N_NODES) return;
    const int nid = warp;
    const int hl = lane & 3;
    const float er_l = __ldg(&er[nid * 4 + hl]);
    int i = __ldg(&g_rptr[nid]);
    const int end = __ldg(&g_rptr[nid + 1]);
    const uint2* f2 = (const uint2*)feat;

    float den_l = 0.f;
    float4 accA = make_float4(0, 0, 0, 0);
    float4 accB = make_float4(0, 0, 0, 0);

    if (!LAST) {
        const int hsel = lane >> 3;                 // head of cols 4l..4l+3 (F=32)
#pragma unroll 4
        for (; i < end; i++) {
            int s = __ldg(&g_srcs[i]);
            float t = __ldg(&el[s * 4 + hl]) + er_l;
            float ex_l = __expf(fmaxf(t, 0.2f * t));
            den_l += ex_l;
            float ex = __shfl_sync(~0u, ex_l, hsel, 4);
            uint2 u = __ldg(&f2[(size_t)s * 32 + lane]);
            float2 fa = __half22float2(*(__half2*)&u.x);
            float2 fb = __half22float2(*(__half2*)&u.y);
            accA.x += ex * fa.x; accA.y += ex * fa.y;
            accA.z += ex * fb.x; accA.w += ex * fb.y;
        }
        float inv_l = 1.f / fmaxf(den_l, 1e-9f);
        float invh = __shfl_sync(~0u, inv_l, hsel, 4);
        int c0 = 4 * lane;
        float4 bv = *(const float4*)&bias[c0];
        float4 v;
        v.x = accA.x * invh + bv.x;
        v.y = accA.y * invh + bv.y;
        v.z = accA.z * invh + bv.z;
        v.w = accA.w * invh + bv.w;
        v.x = v.x > 0.f ? v.x : expm1f(v.x);
        v.y = v.y > 0.f ? v.y : expm1f(v.y);
        v.z = v.z > 0.f ? v.z : expm1f(v.z);
        v.w = v.w > 0.f ? v.w : expm1f(v.w);
        *(float4*)&out[(size_t)nid * 128 + c0] = v;
    } else {
        const int h0 = lane >> 4;                   // head of cols 4l..4l+3 (F=64)
#pragma unroll 2
        for (; i < end; i++) {
            int s = __ldg(&g_srcs[i]);
            float t = __ldg(&el[s * 4 + hl]) + er_l;
            float ex_l = __expf(fmaxf(t, 0.2f * t));
            den_l += ex_l;
            float exA = __shfl_sync(~0u, ex_l, h0, 4);
            float exB = __shfl_sync(~0u, ex_l, h0 + 2, 4);
            const uint2* fr = &f2[(size_t)s * 64];
            uint2 uA = __ldg(&fr[lane]);            // cols 4l..4l+3   (head h0)
            uint2 uB = __ldg(&fr[32 + lane]);       // cols 128+4l..   (head h0+2)
            float2 a0 = __half22float2(*(__half2*)&uA.x);
            float2 a1 = __half22float2(*(__half2*)&uA.y);
            float2 b0 = __half22float2(*(__half2*)&uB.x);
            float2 b1 = __half22float2(*(__half2*)&uB.y);
            accA.x += exA * a0.x; accA.y += exA * a0.y;
            accA.z += exA * a1.x; accA.w += exA * a1.y;
            accB.x += exB * b0.x; accB.y += exB * b0.y;
            accB.z += exB * b1.x; accB.w += exB * b1.y;
        }
        float inv_l = 1.f / fmaxf(den_l, 1e-9f);
        float invA = __shfl_sync(~0u, inv_l, h0, 4);
        float invB = __shfl_sync(~0u, inv_l, h0 + 2, 4);
        int c0 = 4 * lane;
        float p[4];
        p[0] = accA.x * invA + bias[c0]     + accB.x * invB + bias[128 + c0];
        p[1] = accA.y * invA + bias[c0 + 1] + accB.y * invB + bias[128 + c0 + 1];
        p[2] = accA.z * invA + bias[c0 + 2] + accB.z * invB + bias[128 + c0 + 2];
        p[3] = accA.w * invA + bias[c0 + 3] + accB.w * invB + bias[128 + c0 + 3];
#pragma unroll
        for (int k = 0; k < 4; k++) p[k] += __shfl_xor_sync(~0u, p[k], 16);
        if (lane < 16) {
            float4 y = make_float4(0.25f * p[0], 0.25f * p[1], 0.25f * p[2], 0.25f * p[3]);
            *(float4*)&out[(size_t)nid * 64 + c0] = y;   // c0 = 4*lane in [0,64)
        }
    }
}

// ---------------- host -------------------------------------------------------
extern "C" void kernel_launch(void* const* d_in, const int* in_sizes, int n_in,
                              void* d_out, int out_size) {
    const float* x   = (const float*)d_in[0];
    const int*   src = (const int*)d_in[1];
    const int*   dst = (const int*)d_in[2];
    const float *W[4], *al[4], *ar[4], *bb[4];
    for (int i = 0; i < 4; i++) {
        W[i]  = (const float*)d_in[3 + i * 4];
        al[i] = (const float*)d_in[4 + i * 4];
        ar[i] = (const float*)d_in[5 + i * 4];
        bb[i] = (const float*)d_in[6 + i * 4];
    }

    __half* feat;
    float *A, *B, *el, *er;
    cudaGetSymbolAddress((void**)&feat, g_feath);
    cudaGetSymbolAddress((void**)&A,    g_bufA);
    cudaGetSymbolAddress((void**)&B,    g_bufB);
    cudaGetSymbolAddress((void**)&el,   g_el);
    cudaGetSymbolAddress((void**)&er,   g_er);

    const int SMEM = 2 * 128 * 136 * 2 + 2 * 128 * 4;   // 70656 B
    cudaFuncSetAttribute(tc_gemm<32>, cudaFuncAttributeMaxDynamicSharedMemorySize, SMEM);
    cudaFuncSetAttribute(tc_gemm<64>, cudaFuncAttributeMaxDynamicSharedMemorySize, SMEM);

    // ---- CSR build ----
    hist_kernel<<<(N_EDGES + 255) / 256, 256>>>(dst);
    scan_kernel<<<1, 1024>>>();
    scatter_kernel<<<(N_EDGES + 255) / 256, 256>>>(src, dst);

    const int agg_blocks = (N_NODES * 32 + 255) / 256;
    const dim3 g1((N_NODES + 127) / 128, 1), g2((N_NODES + 127) / 128, 2);

    // layer 1
    tc_gemm<32><<<g1, 256, SMEM>>>(x, W[0], al[0], ar[0], feat, el, er);
    gat_agg<false><<<agg_blocks, 256>>>(feat, el, er, bb[0], A);
    // layer 2
    tc_gemm<32><<<g1, 256, SMEM>>>(A, W[1], al[1], ar[1], feat, el, er);
    gat_agg<false><<<agg_blocks, 256>>>(feat, el, er, bb[1], B);
    // layer 3
    tc_gemm<32><<<g1, 256, SMEM>>>(B, W[2], al[2], ar[2], feat, el, er);
    gat_agg<false><<<agg_blocks, 256>>>(feat, el, er, bb[2], A);
    // layer 4 (fused head-mean)
    tc_gemm<64><<<g2, 256, SMEM>>>(A, W[3], al[3], ar[3], feat, el, er);
    gat_agg<true><<<agg_blocks, 256>>>(feat, el, er, bb[3], (float*)d_out);
}

// round 7
// speedup vs baseline: 1.3326x; 1.0125x over previous
#include <cuda_runtime.h>
#include <cuda_fp16.h>
#include <math.h>

#define N_NODES 50000
#define N_EDGES 800000
#define DIN 128
#define NH 4
#define WT_TILE (128 * 136)   // one prepped W column-tile (halfs)

// ---------------- scratch buffers -------------------------------------------
__device__ __half g_feath[(size_t)N_NODES * 256];  // GEMM output fp16 (max HF=256)
__device__ __half g_x16[(size_t)N_NODES * 128];    // x converted to fp16
__device__ __half g_bufA[(size_t)N_NODES * 128];   // activations fp16
__device__ __half g_bufB[(size_t)N_NODES * 128];
__device__ __half g_wt[5 * WT_TILE];               // prepped W tiles (L1,L2,L3,L4ct0,L4ct1)
__device__ float  g_el[(size_t)N_NODES * NH];
__device__ float  g_er[(size_t)N_NODES * NH];
__device__ int    g_cnt[N_NODES];                  // zero-init; re-zeroed by scan
__device__ int    g_rptr[N_NODES + 1];
__device__ int    g_cursor[N_NODES];
__device__ int    g_srcs[N_EDGES];

// ---------------- x -> fp16 --------------------------------------------------
__global__ void convert_x(const float* __restrict__ x, __half* __restrict__ y) {
    int i = blockIdx.x * blockDim.x + threadIdx.x;   // 8 elems per thread
    const float4* src = (const float4*)x + i * 2;
    float4 a = src[0], b = src[1];
    __half2 h[4];
    h[0] = __floats2half2_rn(a.x, a.y);
    h[1] = __floats2half2_rn(a.z, a.w);
    h[2] = __floats2half2_rn(b.x, b.y);
    h[3] = __floats2half2_rn(b.z, b.w);
    *(uint4*)(y + i * 8) = *(uint4*)h;
}

// ---------------- W prep: fp32 [K][HF] -> fp16 swizzled n-major tiles --------
// tile layout: wt[n*136 + (kp ^ ((n>>3)&3))*2 + b] = W[2kp+b][ct*128+n]
__global__ void wprep(const float* __restrict__ w0, const float* __restrict__ w1,
                      const float* __restrict__ w2, const float* __restrict__ w3) {
    int t = blockIdx.x * 256 + threadIdx.x;          // 0..8191 within tile
    int y = blockIdx.y;                              // 0..4 = tile id
    const float* W; int HF, ct;
    if (y == 0)      { W = w0; HF = 128; ct = 0; }
    else if (y == 1) { W = w1; HF = 128; ct = 0; }
    else if (y == 2) { W = w2; HF = 128; ct = 0; }
    else if (y == 3) { W = w3; HF = 256; ct = 0; }
    else             { W = w3; HF = 256; ct = 1; }
    int n = t & 127, kp = t >> 7;
    int k = 2 * kp;
    float f0 = W[(size_t)k * HF + ct * 128 + n];
    float f1 = W[(size_t)(k + 1) * HF + ct * 128 + n];
    int kps = kp ^ ((n >> 3) & 3);
    *(__half2*)&g_wt[(size_t)y * WT_TILE + n * 136 + kps * 2] = __floats2half2_rn(f0, f1);
}

// ---------------- tensor-core GEMM + fused el/er (fp16 in, fp32 accum) -------
template<int F>
__global__ void __launch_bounds__(256, 2)
tc_gemm(const __half* __restrict__ h16, const __half* __restrict__ wt,
        const float* __restrict__ al, const float* __restrict__ ar,
        __half* __restrict__ feat, float* __restrict__ el,
        float* __restrict__ er) {
    constexpr int HF = 4 * F;
    constexpr int HT = 128 / F;
    extern __shared__ __half smx[];
    __half* As = smx;                      // [128][136] row-major (m,k)
    __half* Bs = smx + 128 * 136;          // prepped tile, linear copy
    float* sAL = (float*)(smx + 2 * 128 * 136);
    float* sAR = sAL + 128;

    const int ct  = blockIdx.y;
    const int n0  = blockIdx.x * 128;
    const int tid = threadIdx.x;
    const int lane = tid & 31;
    const int wid  = tid >> 5;

    if (tid < 128) { sAL[tid] = al[ct * 128 + tid]; sAR[tid] = ar[ct * 128 + tid]; }

    // A tile: 2048 16B chunks (128 rows x 16 chunks), row-clamped
#pragma unroll
    for (int i = 0; i < 8; i++) {
        int id = tid + i * 256;
        int r = id >> 4, c = id & 15;
        int n = n0 + r;
        if (n >= N_NODES) n = 0;                     // clamp; result unused
        *(uint4*)&As[r * 136 + c * 8] = *(const uint4*)&h16[(size_t)n * DIN + c * 8];
    }
    // B tile: linear copy of prepped 2176 16B chunks
    const uint4* wsrc = (const uint4*)(wt + (size_t)ct * WT_TILE);
#pragma unroll
    for (int i = 0; i < 9; i++) {
        int id = tid + i * 256;
        if (id < 2176) ((uint4*)Bs)[id] = wsrc[id];
    }
    __syncthreads();

    const int g = lane >> 2, q = lane & 3;
    const int m0 = wid * 16;
    float acc[16][4];
#pragma unroll
    for (int nt = 0; nt < 16; nt++)
        acc[nt][0] = acc[nt][1] = acc[nt][2] = acc[nt][3] = 0.f;

#pragma unroll
    for (int ks = 0; ks < 8; ks++) {
        unsigned a0 = *(const unsigned*)&As[(m0 + g)     * 136 + ks * 16 + q * 2];
        unsigned a1 = *(const unsigned*)&As[(m0 + 8 + g) * 136 + ks * 16 + q * 2];
        unsigned a2 = *(const unsigned*)&As[(m0 + g)     * 136 + ks * 16 + 8 + q * 2];
        unsigned a3 = *(const unsigned*)&As[(m0 + 8 + g) * 136 + ks * 16 + 8 + q * 2];
#pragma unroll
        for (int nt = 0; nt < 16; nt++) {
            int n = nt * 8 + g;
            int sw = nt & 3;
            int p0 = (ks * 8 + q) ^ sw;
            int p1 = (ks * 8 + 4 + q) ^ sw;
            unsigned b0 = *(const unsigned*)&Bs[n * 136 + p0 * 2];
            unsigned b1 = *(const unsigned*)&Bs[n * 136 + p1 * 2];
            asm volatile(
                "mma.sync.aligned.m16n8k16.row.col.f32.f16.f16.f32 "
                "{%0,%1,%2,%3}, {%4,%5,%6,%7}, {%8,%9}, {%0,%1,%2,%3};"
                : "+f"(acc[nt][0]), "+f"(acc[nt][1]), "+f"(acc[nt][2]), "+f"(acc[nt][3])
                : "r"(a0), "r"(a1), "r"(a2), "r"(a3), "r"(b0), "r"(b1));
        }
    }

    const int rA = n0 + m0 + g, rB = rA + 8;

#pragma unroll
    for (int nt = 0; nt < 16; nt++) {
        int col = ct * 128 + nt * 8 + q * 2;
        if (rA < N_NODES)
            *(__half2*)&feat[(size_t)rA * HF + col] = __floats2half2_rn(acc[nt][0], acc[nt][1]);
        if (rB < N_NODES)
            *(__half2*)&feat[(size_t)rB * HF + col] = __floats2half2_rn(acc[nt][2], acc[nt][3]);
    }
#pragma unroll
    for (int hh = 0; hh < HT; hh++) {
        float plA = 0.f, prA = 0.f, plB = 0.f, prB = 0.f;
#pragma unroll
        for (int j = 0; j < F / 8; j++) {
            int nt = hh * (F / 8) + j;
            int c = nt * 8 + q * 2;
            float al0 = sAL[c], al1 = sAL[c + 1];
            float ar0 = sAR[c], ar1 = sAR[c + 1];
            plA += acc[nt][0] * al0 + acc[nt][1] * al1;
            prA += acc[nt][0] * ar0 + acc[nt][1] * ar1;
            plB += acc[nt][2] * al0 + acc[nt][3] * al1;
            prB += acc[nt][2] * ar0 + acc[nt][3] * ar1;
        }
        plA += __shfl_xor_sync(~0u, plA, 1); plA += __shfl_xor_sync(~0u, plA, 2);
        prA += __shfl_xor_sync(~0u, prA, 1); prA += __shfl_xor_sync(~0u, prA, 2);
        plB += __shfl_xor_sync(~0u, plB, 1); plB += __shfl_xor_sync(~0u, plB, 2);
        prB += __shfl_xor_sync(~0u, prB, 1); prB += __shfl_xor_sync(~0u, prB, 2);
        if (q == 0) {
            int head = ct * HT + hh;
            if (rA < N_NODES) { el[rA * 4 + head] = plA; er[rA * 4 + head] = prA; }
            if (rB < N_NODES) { el[rB * 4 + head] = plB; er[rB * 4 + head] = prB; }
        }
    }
}

// ---------------- CSR build --------------------------------------------------
__global__ void hist_kernel(const int* __restrict__ dst) {
    int e = blockIdx.x * blockDim.x + threadIdx.x;
    if (e < N_EDGES) atomicAdd(&g_cnt[dst[e]], 1);
}
__global__ void scan_kernel() {
    __shared__ int wsum[32];
    __shared__ int carry;
    int t = threadIdx.x;
    if (t == 0) carry = 0;
    __syncthreads();
    for (int base = 0; base < N_NODES; base += 1024) {
        int i = base + t;
        int v = (i < N_NODES) ? g_cnt[i] : 0;
        if (i < N_NODES) g_cnt[i] = 0;           // reset for next call
        int x = v;
#pragma unroll
        for (int o = 1; o < 32; o <<= 1) {
            int y = __shfl_up_sync(~0u, x, o);
            if ((t & 31) >= o) x += y;
        }
        if ((t & 31) == 31) wsum[t >> 5] = x;
        __syncthreads();
        if (t < 32) {
            int s = wsum[t];
#pragma unroll
            for (int o = 1; o < 32; o <<= 1) {
                int y = __shfl_up_sync(~0u, s, o);
                if (t >= o) s += y;
            }
            wsum[t] = s;
        }
        __syncthreads();
        int warpoff = (t >= 32) ? wsum[(t >> 5) - 1] : 0;
        int excl = x + warpoff - v + carry;
        if (i < N_NODES) { g_rptr[i] = excl; g_cursor[i] = excl; }
        int btot = wsum[31];
        __syncthreads();
        if (t == 0) carry += btot;
        __syncthreads();
    }
    if (t == 0) g_rptr[N_NODES] = N_EDGES;
}
__global__ void scatter_kernel(const int* __restrict__ src, const int* __restrict__ dst) {
    int e = blockIdx.x * blockDim.x + threadIdx.x;
    if (e >= N_EDGES) return;
    int pos = atomicAdd(&g_cursor[dst[e]], 1);
    g_srcs[pos] = src[e];
}

// ---------------- GAT aggregation: one warp per dst node ---------------------
// Lane-specialized: lane l computes the exponent only for head (l&3); one exp
// per edge per warp. Lane l gathers feat cols 4l..4l+3 (LDG.64). fp16 output
// for hidden layers, fp32 head-mean for the last.
template<bool LAST>
__global__ void gat_agg(const __half* __restrict__ feat, const float* __restrict__ el,
                        const float* __restrict__ er, const float* __restrict__ bias,
                        void* __restrict__ outv) {
    int warp = (blockIdx.x * blockDim.x + threadIdx.x) >> 5;
    int lane = threadIdx.x & 31;
    if (warp >= N_NODES) return;
    const int nid = warp;
    const int hl = lane & 3;
    const float er_l = __ldg(&er[nid * 4 + hl]);
    int i = __ldg(&g_rptr[nid]);
    const int end = __ldg(&g_rptr[nid + 1]);
    const uint2* f2 = (const uint2*)feat;

    float den_l = 0.f;
    float4 accA = make_float4(0, 0, 0, 0);
    float4 accB = make_float4(0, 0, 0, 0);

    if (!LAST) {
        const int hsel = lane >> 3;
#pragma unroll 4
        for (; i < end; i++) {
            int s = __ldg(&g_srcs[i]);
            float t = __ldg(&el[s * 4 + hl]) + er_l;
            float ex_l = __expf(fmaxf(t, 0.2f * t));
            den_l += ex_l;
            float ex = __shfl_sync(~0u, ex_l, hsel, 4);
            uint2 u = __ldg(&f2[(size_t)s * 32 + lane]);
            float2 fa = __half22float2(*(__half2*)&u.x);
            float2 fb = __half22float2(*(__half2*)&u.y);
            accA.x += ex * fa.x; accA.y += ex * fa.y;
            accA.z += ex * fb.x; accA.w += ex * fb.y;
        }
        float inv_l = 1.f / fmaxf(den_l, 1e-9f);
        float invh = __shfl_sync(~0u, inv_l, hsel, 4);
        int c0 = 4 * lane;
        float4 bv = *(const float4*)&bias[c0];
        float4 v;
        v.x = accA.x * invh + bv.x;
        v.y = accA.y * invh + bv.y;
        v.z = accA.z * invh + bv.z;
        v.w = accA.w * invh + bv.w;
        v.x = v.x > 0.f ? v.x : expm1f(v.x);
        v.y = v.y > 0.f ? v.y : expm1f(v.y);
        v.z = v.z > 0.f ? v.z : expm1f(v.z);
        v.w = v.w > 0.f ? v.w : expm1f(v.w);
        __half2 h01 = __floats2half2_rn(v.x, v.y);
        __half2 h23 = __floats2half2_rn(v.z, v.w);
        uint2 pack = make_uint2(*(unsigned*)&h01, *(unsigned*)&h23);
        ((uint2*)outv)[(size_t)nid * 32 + lane] = pack;
    } else {
        const int h0 = lane >> 4;
#pragma unroll 2
        for (; i < end; i++) {
            int s = __ldg(&g_srcs[i]);
            float t = __ldg(&el[s * 4 + hl]) + er_l;
            float ex_l = __expf(fmaxf(t, 0.2f * t));
            den_l += ex_l;
            float exA = __shfl_sync(~0u, ex_l, h0, 4);
            float exB = __shfl_sync(~0u, ex_l, h0 + 2, 4);
            const uint2* fr = &f2[(size_t)s * 64];
            uint2 uA = __ldg(&fr[lane]);
            uint2 uB = __ldg(&fr[32 + lane]);
            float2 a0 = __half22float2(*(__half2*)&uA.x);
            float2 a1 = __half22float2(*(__half2*)&uA.y);
            float2 b0 = __half22float2(*(__half2*)&uB.x);
            float2 b1 = __half22float2(*(__half2*)&uB.y);
            accA.x += exA * a0.x; accA.y += exA * a0.y;
            accA.z += exA * a1.x; accA.w += exA * a1.y;
            accB.x += exB * b0.x; accB.y += exB * b0.y;
            accB.z += exB * b1.x; accB.w += exB * b1.y;
        }
        float* out = (float*)outv;
        float inv_l = 1.f / fmaxf(den_l, 1e-9f);
        float invA = __shfl_sync(~0u, inv_l, h0, 4);
        float invB = __shfl_sync(~0u, inv_l, h0 + 2, 4);
        int c0 = 4 * lane;
        float p[4];
        p[0] = accA.x * invA + bias[c0]     + accB.x * invB + bias[128 + c0];
        p[1] = accA.y * invA + bias[c0 + 1] + accB.y * invB + bias[128 + c0 + 1];
        p[2] = accA.z * invA + bias[c0 + 2] + accB.z * invB + bias[128 + c0 + 2];
        p[3] = accA.w * invA + bias[c0 + 3] + accB.w * invB + bias[128 + c0 + 3];
#pragma unroll
        for (int k = 0; k < 4; k++) p[k] += __shfl_xor_sync(~0u, p[k], 16);
        if (lane < 16) {
            float4 y = make_float4(0.25f * p[0], 0.25f * p[1], 0.25f * p[2], 0.25f * p[3]);
            *(float4*)&out[(size_t)nid * 64 + c0] = y;
        }
    }
}

// ---------------- host -------------------------------------------------------
extern "C" void kernel_launch(void* const* d_in, const int* in_sizes, int n_in,
                              void* d_out, int out_size) {
    const float* x   = (const float*)d_in[0];
    const int*   src = (const int*)d_in[1];
    const int*   dst = (const int*)d_in[2];
    const float *W[4], *al[4], *ar[4], *bb[4];
    for (int i = 0; i < 4; i++) {
        W[i]  = (const float*)d_in[3 + i * 4];
        al[i] = (const float*)d_in[4 + i * 4];
        ar[i] = (const float*)d_in[5 + i * 4];
        bb[i] = (const float*)d_in[6 + i * 4];
    }

    __half *feat, *x16, *A, *B, *wt;
    float *el, *er;
    cudaGetSymbolAddress((void**)&feat, g_feath);
    cudaGetSymbolAddress((void**)&x16,  g_x16);
    cudaGetSymbolAddress((void**)&A,    g_bufA);
    cudaGetSymbolAddress((void**)&B,    g_bufB);
    cudaGetSymbolAddress((void**)&wt,   g_wt);
    cudaGetSymbolAddress((void**)&el,   g_el);
    cudaGetSymbolAddress((void**)&er,   g_er);

    const int SMEM = 2 * 128 * 136 * 2 + 2 * 128 * 4;   // 70656 B
    cudaFuncSetAttribute(tc_gemm<32>, cudaFuncAttributeMaxDynamicSharedMemorySize, SMEM);
    cudaFuncSetAttribute(tc_gemm<64>, cudaFuncAttributeMaxDynamicSharedMemorySize, SMEM);

    // ---- prep: x->fp16, W tiles; CSR build ----
    convert_x<<<N_NODES * DIN / (256 * 8), 256>>>(x, x16);
    wprep<<<dim3(32, 5), 256>>>(W[0], W[1], W[2], W[3]);
    hist_kernel<<<(N_EDGES + 255) / 256, 256>>>(dst);
    scan_kernel<<<1, 1024>>>();
    scatter_kernel<<<(N_EDGES + 255) / 256, 256>>>(src, dst);

    const int agg_blocks = (N_NODES * 32 + 255) / 256;
    const dim3 g1((N_NODES + 127) / 128, 1), g2((N_NODES + 127) / 128, 2);

    // layer 1
    tc_gemm<32><<<g1, 256, SMEM>>>(x16, wt + 0 * WT_TILE, al[0], ar[0], feat, el, er);
    gat_agg<false><<<agg_blocks, 256>>>(feat, el, er, bb[0], A);
    // layer 2
    tc_gemm<32><<<g1, 256, SMEM>>>(A, wt + 1 * WT_TILE, al[1], ar[1], feat, el, er);
    gat_agg<false><<<agg_blocks, 256>>>(feat, el, er, bb[1], B);
    // layer 3
    tc_gemm<32><<<g1, 256, SMEM>>>(B, wt + 2 * WT_TILE, al[2], ar[2], feat, el, er);
    gat_agg<false><<<agg_blocks, 256>>>(feat, el, er, bb[2], A);
    // layer 4 (fused head-mean)
    tc_gemm<64><<<g2, 256, SMEM>>>(A, wt + 3 * WT_TILE, al[3], ar[3], feat, el, er);
    gat_agg<true><<<agg_blocks, 256>>>(feat, el, er, bb[3], d_out);
}

// round 8
// speedup vs baseline: 1.5296x; 1.1478x over previous
#include <cuda_runtime.h>
#include <cuda_fp16.h>
#include <math.h>

#define N_NODES 50000
#define N_EDGES 800000
#define DIN 128
#define NH 4
#define WT_TILE (128 * 136)   // one prepped W column-tile (halfs)

// ---------------- scratch buffers -------------------------------------------
__device__ __half g_feath[(size_t)N_NODES * 256];  // GEMM output fp16 (max HF=256)
__device__ __half g_x16[(size_t)N_NODES * 128];    // x converted to fp16
__device__ __half g_bufA[(size_t)N_NODES * 128];   // activations fp16
__device__ __half g_bufB[(size_t)N_NODES * 128];
__device__ __half g_wt[5 * WT_TILE];               // prepped W tiles
__device__ float  g_el[(size_t)N_NODES * NH];
__device__ float  g_er[(size_t)N_NODES * NH];
__device__ int    g_cnt[N_NODES];                  // zero-init; re-zeroed by scan1
__device__ int    g_rptr[N_NODES + 1];
__device__ int    g_cursor[N_NODES];
__device__ int    g_bsum[128];
__device__ int    g_srcs[N_EDGES];

// ---------------- x -> fp16 --------------------------------------------------
__global__ void convert_x(const float* __restrict__ x, __half* __restrict__ y) {
    int i = blockIdx.x * blockDim.x + threadIdx.x;   // 8 elems per thread
    const float4* src = (const float4*)x + i * 2;
    float4 a = src[0], b = src[1];
    __half2 h[4];
    h[0] = __floats2half2_rn(a.x, a.y);
    h[1] = __floats2half2_rn(a.z, a.w);
    h[2] = __floats2half2_rn(b.x, b.y);
    h[3] = __floats2half2_rn(b.z, b.w);
    *(uint4*)(y + i * 8) = *(uint4*)h;
}

// ---------------- W prep: fp32 [K][HF] -> fp16 swizzled n-major tiles --------
__global__ void wprep(const float* __restrict__ w0, const float* __restrict__ w1,
                      const float* __restrict__ w2, const float* __restrict__ w3) {
    int t = blockIdx.x * 256 + threadIdx.x;
    int y = blockIdx.y;
    const float* W; int HF, ct;
    if (y == 0)      { W = w0; HF = 128; ct = 0; }
    else if (y == 1) { W = w1; HF = 128; ct = 0; }
    else if (y == 2) { W = w2; HF = 128; ct = 0; }
    else if (y == 3) { W = w3; HF = 256; ct = 0; }
    else             { W = w3; HF = 256; ct = 1; }
    int n = t & 127, kp = t >> 7;
    int k = 2 * kp;
    float f0 = W[(size_t)k * HF + ct * 128 + n];
    float f1 = W[(size_t)(k + 1) * HF + ct * 128 + n];
    int kps = kp ^ ((n >> 3) & 3);
    *(__half2*)&g_wt[(size_t)y * WT_TILE + n * 136 + kps * 2] = __floats2half2_rn(f0, f1);
}

// ---------------- tensor-core GEMM + fused el/er (fp16 in, fp32 accum) -------
template<int F>
__global__ void __launch_bounds__(256, 2)
tc_gemm(const __half* __restrict__ h16, const __half* __restrict__ wt,
        const float* __restrict__ al, const float* __restrict__ ar,
        __half* __restrict__ feat, float* __restrict__ el,
        float* __restrict__ er) {
    constexpr int HF = 4 * F;
    constexpr int HT = 128 / F;
    extern __shared__ __half smx[];
    __half* As = smx;                      // [128][136]
    __half* Bs = smx + 128 * 136;          // prepped tile, linear copy
    float* sAL = (float*)(smx + 2 * 128 * 136);
    float* sAR = sAL + 128;

    const int ct  = blockIdx.y;
    const int n0  = blockIdx.x * 128;
    const int tid = threadIdx.x;
    const int lane = tid & 31;
    const int wid  = tid >> 5;

    if (tid < 128) { sAL[tid] = al[ct * 128 + tid]; sAR[tid] = ar[ct * 128 + tid]; }

#pragma unroll
    for (int i = 0; i < 8; i++) {
        int id = tid + i * 256;
        int r = id >> 4, c = id & 15;
        int n = n0 + r;
        if (n >= N_NODES) n = 0;
        *(uint4*)&As[r * 136 + c * 8] = *(const uint4*)&h16[(size_t)n * DIN + c * 8];
    }
    const uint4* wsrc = (const uint4*)(wt + (size_t)ct * WT_TILE);
#pragma unroll
    for (int i = 0; i < 9; i++) {
        int id = tid + i * 256;
        if (id < 2176) ((uint4*)Bs)[id] = wsrc[id];
    }
    __syncthreads();

    const int g = lane >> 2, q = lane & 3;
    const int m0 = wid * 16;
    float acc[16][4];
#pragma unroll
    for (int nt = 0; nt < 16; nt++)
        acc[nt][0] = acc[nt][1] = acc[nt][2] = acc[nt][3] = 0.f;

#pragma unroll
    for (int ks = 0; ks < 8; ks++) {
        unsigned a0 = *(const unsigned*)&As[(m0 + g)     * 136 + ks * 16 + q * 2];
        unsigned a1 = *(const unsigned*)&As[(m0 + 8 + g) * 136 + ks * 16 + q * 2];
        unsigned a2 = *(const unsigned*)&As[(m0 + g)     * 136 + ks * 16 + 8 + q * 2];
        unsigned a3 = *(const unsigned*)&As[(m0 + 8 + g) * 136 + ks * 16 + 8 + q * 2];
#pragma unroll
        for (int nt = 0; nt < 16; nt++) {
            int n = nt * 8 + g;
            int sw = nt & 3;
            int p0 = (ks * 8 + q) ^ sw;
            int p1 = (ks * 8 + 4 + q) ^ sw;
            unsigned b0 = *(const unsigned*)&Bs[n * 136 + p0 * 2];
            unsigned b1 = *(const unsigned*)&Bs[n * 136 + p1 * 2];
            asm volatile(
                "mma.sync.aligned.m16n8k16.row.col.f32.f16.f16.f32 "
                "{%0,%1,%2,%3}, {%4,%5,%6,%7}, {%8,%9}, {%0,%1,%2,%3};"
                : "+f"(acc[nt][0]), "+f"(acc[nt][1]), "+f"(acc[nt][2]), "+f"(acc[nt][3])
                : "r"(a0), "r"(a1), "r"(a2), "r"(a3), "r"(b0), "r"(b1));
        }
    }

    const int rA = n0 + m0 + g, rB = rA + 8;

#pragma unroll
    for (int nt = 0; nt < 16; nt++) {
        int col = ct * 128 + nt * 8 + q * 2;
        if (rA < N_NODES)
            *(__half2*)&feat[(size_t)rA * HF + col] = __floats2half2_rn(acc[nt][0], acc[nt][1]);
        if (rB < N_NODES)
            *(__half2*)&feat[(size_t)rB * HF + col] = __floats2half2_rn(acc[nt][2], acc[nt][3]);
    }
#pragma unroll
    for (int hh = 0; hh < HT; hh++) {
        float plA = 0.f, prA = 0.f, plB = 0.f, prB = 0.f;
#pragma unroll
        for (int j = 0; j < F / 8; j++) {
            int nt = hh * (F / 8) + j;
            int c = nt * 8 + q * 2;
            float al0 = sAL[c], al1 = sAL[c + 1];
            float ar0 = sAR[c], ar1 = sAR[c + 1];
            plA += acc[nt][0] * al0 + acc[nt][1] * al1;
            prA += acc[nt][0] * ar0 + acc[nt][1] * ar1;
            plB += acc[nt][2] * al0 + acc[nt][3] * al1;
            prB += acc[nt][2] * ar0 + acc[nt][3] * ar1;
        }
        plA += __shfl_xor_sync(~0u, plA, 1); plA += __shfl_xor_sync(~0u, plA, 2);
        prA += __shfl_xor_sync(~0u, prA, 1); prA += __shfl_xor_sync(~0u, prA, 2);
        plB += __shfl_xor_sync(~0u, plB, 1); plB += __shfl_xor_sync(~0u, plB, 2);
        prB += __shfl_xor_sync(~0u, prB, 1); prB += __shfl_xor_sync(~0u, prB, 2);
        if (q == 0) {
            int head = ct * HT + hh;
            if (rA < N_NODES) { el[rA * 4 + head] = plA; er[rA * 4 + head] = prA; }
            if (rB < N_NODES) { el[rB * 4 + head] = plB; er[rB * 4 + head] = prB; }
        }
    }
}

// ---------------- CSR build (parallel 3-kernel scan) --------------------------
__global__ void hist_kernel(const int* __restrict__ dst) {
    int e = blockIdx.x * blockDim.x + threadIdx.x;
    if (e < N_EDGES) atomicAdd(&g_cnt[dst[e]], 1);
}
// per-block (512-wide) exclusive scan via warp shuffles; re-zeroes g_cnt
__global__ void scan1_kernel() {
    __shared__ int ws[16];
    int t = threadIdx.x;
    int lane = t & 31, w = t >> 5;
    int i = blockIdx.x * 512 + t;
    int v = (i < N_NODES) ? g_cnt[i] : 0;
    if (i < N_NODES) g_cnt[i] = 0;                  // reset for next call
    int x = v;
#pragma unroll
    for (int o = 1; o < 32; o <<= 1) {
        int y = __shfl_up_sync(~0u, x, o);
        if (lane >= o) x += y;
    }
    if (lane == 31) ws[w] = x;
    __syncthreads();
    if (t < 16) {
        int s = ws[t];
#pragma unroll
        for (int o = 1; o < 16; o <<= 1) {
            int y = __shfl_up_sync(0xffffu, s, o, 16);
            if (t >= o) s += y;
        }
        ws[t] = s;
    }
    __syncthreads();
    int off = (w > 0) ? ws[w - 1] : 0;
    int incl = x + off;
    if (i < N_NODES) g_rptr[i] = incl - v;          // block-local exclusive
    if (t == 511) g_bsum[blockIdx.x] = incl;        // block total
}
// single tiny block: exclusive scan of 98 block sums
__global__ void scan2_kernel(int nb) {
    int t = threadIdx.x;                             // 128 threads
    int v = (t < nb) ? g_bsum[t] : 0;
    int lane = t & 31, w = t >> 5;
    __shared__ int ws[4];
    int x = v;
#pragma unroll
    for (int o = 1; o < 32; o <<= 1) {
        int y = __shfl_up_sync(~0u, x, o);
        if (lane >= o) x += y;
    }
    if (lane == 31) ws[w] = x;
    __syncthreads();
    if (t < 4) {
        int s = ws[t];
#pragma unroll
        for (int o = 1; o < 4; o <<= 1) {
            int y = __shfl_up_sync(0xfu, s, o, 4);
            if (t >= o) s += y;
        }
        ws[t] = s;
    }
    __syncthreads();
    int off = (w > 0) ? ws[w - 1] : 0;
    if (t < nb) g_bsum[t] = x + off - v;            // exclusive
}
__global__ void scan3_kernel() {
    int i = blockIdx.x * blockDim.x + threadIdx.x;
    if (i < N_NODES) {
        int r = g_rptr[i] + g_bsum[i >> 9];
        g_rptr[i] = r;
        g_cursor[i] = r;
    }
    if (i == 0) g_rptr[N_NODES] = N_EDGES;
}
__global__ void scatter_kernel(const int* __restrict__ src, const int* __restrict__ dst) {
    int e = blockIdx.x * blockDim.x + threadIdx.x;
    if (e >= N_EDGES) return;
    int pos = atomicAdd(&g_cursor[dst[e]], 1);
    g_srcs[pos] = src[e];
}

// ---------------- GAT aggregation: one warp per dst node ---------------------
template<bool LAST>
__global__ void gat_agg(const __half* __restrict__ feat, const float* __restrict__ el,
                        const float* __restrict__ er, const float* __restrict__ bias,
                        void* __restrict__ outv) {
    int warp = (blockIdx.x * blockDim.x + threadIdx.x) >> 5;
    int lane = threadIdx.x & 31;
    if (warp >= N_NODES) return;
    const int nid = warp;
    const int hl = lane & 3;
    const float er_l = __ldg(&er[nid * 4 + hl]);
    int i = __ldg(&g_rptr[nid]);
    const int end = __ldg(&g_rptr[nid + 1]);
    const uint2* f2 = (const uint2*)feat;

    float den_l = 0.f;
    float4 accA = make_float4(0, 0, 0, 0);
    float4 accB = make_float4(0, 0, 0, 0);

    if (!LAST) {
        const int hsel = lane >> 3;
#pragma unroll 4
        for (; i < end; i++) {
            int s = __ldg(&g_srcs[i]);
            float t = __ldg(&el[s * 4 + hl]) + er_l;
            float ex_l = __expf(fmaxf(t, 0.2f * t));
            den_l += ex_l;
            float ex = __shfl_sync(~0u, ex_l, hsel, 4);
            uint2 u = __ldg(&f2[(size_t)s * 32 + lane]);
            float2 fa = __half22float2(*(__half2*)&u.x);
            float2 fb = __half22float2(*(__half2*)&u.y);
            accA.x += ex * fa.x; accA.y += ex * fa.y;
            accA.z += ex * fb.x; accA.w += ex * fb.y;
        }
        float inv_l = 1.f / fmaxf(den_l, 1e-9f);
        float invh = __shfl_sync(~0u, inv_l, hsel, 4);
        int c0 = 4 * lane;
        float4 bv = *(const float4*)&bias[c0];
        float4 v;
        v.x = accA.x * invh + bv.x;
        v.y = accA.y * invh + bv.y;
        v.z = accA.z * invh + bv.z;
        v.w = accA.w * invh + bv.w;
        v.x = v.x > 0.f ? v.x : expm1f(v.x);
        v.y = v.y > 0.f ? v.y : expm1f(v.y);
        v.z = v.z > 0.f ? v.z : expm1f(v.z);
        v.w = v.w > 0.f ? v.w : expm1f(v.w);
        __half2 h01 = __floats2half2_rn(v.x, v.y);
        __half2 h23 = __floats2half2_rn(v.z, v.w);
        uint2 pack = make_uint2(*(unsigned*)&h01, *(unsigned*)&h23);
        ((uint2*)outv)[(size_t)nid * 32 + lane] = pack;
    } else {
        const int h0 = lane >> 4;
#pragma unroll 2
        for (; i < end; i++) {
            int s = __ldg(&g_srcs[i]);
            float t = __ldg(&el[s * 4 + hl]) + er_l;
            float ex_l = __expf(fmaxf(t, 0.2f * t));
            den_l += ex_l;
            float exA = __shfl_sync(~0u, ex_l, h0, 4);
            float exB = __shfl_sync(~0u, ex_l, h0 + 2, 4);
            const uint2* fr = &f2[(size_t)s * 64];
            uint2 uA = __ldg(&fr[lane]);
            uint2 uB = __ldg(&fr[32 + lane]);
            float2 a0 = __half22float2(*(__half2*)&uA.x);
            float2 a1 = __half22float2(*(__half2*)&uA.y);
            float2 b0 = __half22float2(*(__half2*)&uB.x);
            float2 b1 = __half22float2(*(__half2*)&uB.y);
            accA.x += exA * a0.x; accA.y += exA * a0.y;
            accA.z += exA * a1.x; accA.w += exA * a1.y;
            accB.x += exB * b0.x; accB.y += exB * b0.y;
            accB.z += exB * b1.x; accB.w += exB * b1.y;
        }
        float* out = (float*)outv;
        float inv_l = 1.f / fmaxf(den_l, 1e-9f);
        float invA = __shfl_sync(~0u, inv_l, h0, 4);
        float invB = __shfl_sync(~0u, inv_l, h0 + 2, 4);
        int c0 = 4 * lane;
        float p[4];
        p[0] = accA.x * invA + bias[c0]     + accB.x * invB + bias[128 + c0];
        p[1] = accA.y * invA + bias[c0 + 1] + accB.y * invB + bias[128 + c0 + 1];
        p[2] = accA.z * invA + bias[c0 + 2] + accB.z * invB + bias[128 + c0 + 2];
        p[3] = accA.w * invA + bias[c0 + 3] + accB.w * invB + bias[128 + c0 + 3];
#pragma unroll
        for (int k = 0; k < 4; k++) p[k] += __shfl_xor_sync(~0u, p[k], 16);
        if (lane < 16) {
            float4 y = make_float4(0.25f * p[0], 0.25f * p[1], 0.25f * p[2], 0.25f * p[3]);
            *(float4*)&out[(size_t)nid * 64 + c0] = y;
        }
    }
}

// ---------------- host -------------------------------------------------------
extern "C" void kernel_launch(void* const* d_in, const int* in_sizes, int n_in,
                              void* d_out, int out_size) {
    const float* x   = (const float*)d_in[0];
    const int*   src = (const int*)d_in[1];
    const int*   dst = (const int*)d_in[2];
    const float *W[4], *al[4], *ar[4], *bb[4];
    for (int i = 0; i < 4; i++) {
        W[i]  = (const float*)d_in[3 + i * 4];
        al[i] = (const float*)d_in[4 + i * 4];
        ar[i] = (const float*)d_in[5 + i * 4];
        bb[i] = (const float*)d_in[6 + i * 4];
    }

    __half *feat, *x16, *A, *B, *wt;
    float *el, *er;
    cudaGetSymbolAddress((void**)&feat, g_feath);
    cudaGetSymbolAddress((void**)&x16,  g_x16);
    cudaGetSymbolAddress((void**)&A,    g_bufA);
    cudaGetSymbolAddress((void**)&B,    g_bufB);
    cudaGetSymbolAddress((void**)&wt,   g_wt);
    cudaGetSymbolAddress((void**)&el,   g_el);
    cudaGetSymbolAddress((void**)&er,   g_er);

    const int SMEM = 2 * 128 * 136 * 2 + 2 * 128 * 4;   // 70656 B
    cudaFuncSetAttribute(tc_gemm<32>, cudaFuncAttributeMaxDynamicSharedMemorySize, SMEM);
    cudaFuncSetAttribute(tc_gemm<64>, cudaFuncAttributeMaxDynamicSharedMemorySize, SMEM);

    // ---- prep: x->fp16, W tiles; CSR build (parallel scan) ----
    convert_x<<<N_NODES * DIN / (256 * 8), 256>>>(x, x16);
    wprep<<<dim3(32, 5), 256>>>(W[0], W[1], W[2], W[3]);
    const int nb = (N_NODES + 511) / 512;               // 98
    hist_kernel<<<(N_EDGES + 511) / 512, 512>>>(dst);
    scan1_kernel<<<nb, 512>>>();
    scan2_kernel<<<1, 128>>>(nb);
    scan3_kernel<<<(N_NODES + 511) / 512, 512>>>();
    scatter_kernel<<<(N_EDGES + 511) / 512, 512>>>(src, dst);

    const int agg_blocks = (N_NODES * 32 + 255) / 256;
    const dim3 g1((N_NODES + 127) / 128, 1), g2((N_NODES + 127) / 128, 2);

    // layer 1
    tc_gemm<32><<<g1, 256, SMEM>>>(x16, wt + 0 * WT_TILE, al[0], ar[0], feat, el, er);
    gat_agg<false><<<agg_blocks, 256>>>(feat, el, er, bb[0], A);
    // layer 2
    tc_gemm<32><<<g1, 256, SMEM>>>(A, wt + 1 * WT_TILE, al[1], ar[1], feat, el, er);
    gat_agg<false><<<agg_blocks, 256>>>(feat, el, er, bb[1], B);
    // layer 3
    tc_gemm<32><<<g1, 256, SMEM>>>(B, wt + 2 * WT_TILE, al[2], ar[2], feat, el, er);
    gat_agg<false><<<agg_blocks, 256>>>(feat, el, er, bb[2], A);
    // layer 4 (fused head-mean)
    tc_gemm<64><<<g2, 256, SMEM>>>(A, wt + 3 * WT_TILE, al[3], ar[3], feat, el, er);
    gat_agg<true><<<agg_blocks, 256>>>(feat, el, er, bb[3], d_out);
}